// round 16
// baseline (speedup 1.0000x reference)
#include <cuda_runtime.h>
#include <math.h>

#define NXX   512
#define NWW   512
#define NYY   256
#define NWUP  128
#define NB    1024
#define NHR   32
#define TT    (NWUP + 1 + NHR)          // 161

#define X_SIZE   ((size_t)TT * NB * NXX)
#define L_OFF    (X_SIZE)
#define L_SIZE   ((size_t)NWUP * NB * NWW)
#define Y_OFF    (L_OFF + L_SIZE)

#define CROWS 32
#define NCTA  128

// ---- packed tf32 weight buffers (pair-interleaved B-fragment order) ----
#define KT_WQ 32
#define KT_L1 96
#define KT_L2 64
#define KT_RZ 128
#define KT_NI 64
#define KT_NH 64
#define KT_P1 64
#define KT_P2 64
#define OFF_WQ 0
#define SZ_WQ  (64 * KT_WQ * 64)
#define OFF_L1 (OFF_WQ + SZ_WQ)
#define SZ_L1  (64 * KT_L1 * 64)
#define OFF_L2 (OFF_L1 + SZ_L1)
#define SZ_L2  (64 * KT_L2 * 64)
#define OFF_RZ (OFF_L2 + SZ_L2)
#define SZ_RZ  (128 * KT_RZ * 64)
#define OFF_NI (OFF_RZ + SZ_RZ)
#define SZ_NI  (64 * KT_NI * 64)
#define OFF_NH (OFF_NI + SZ_NI)
#define SZ_NH  (64 * KT_NH * 64)
#define OFF_P1 (OFF_NH + SZ_NH)
#define SZ_P1  (64 * KT_P1 * 64)
#define OFF_P2 (OFF_P1 + SZ_P1)
#define SZ_P2  (32 * KT_P2 * 64)
#define WPACK_TOTAL (OFF_P2 + SZ_P2)

__device__ unsigned g_wpack[WPACK_TOTAL];

// ---- recurrence smem: ACT [32][1284] tf32 (w/l1:0-511, h:512-1023, y:1024-1279)
//      + HF [32][132] fp32 ----
#define AST     1284
#define HF_OFF  (CROWS * AST)
#define SMEM_UNITS (HF_OFF + CROWS * 132)

#define PROJ_ROWS 64
#define PROJ_SMEM_UNITS (PROJ_ROWS * 516)

__device__ __forceinline__ float sigm(float x) { return 1.0f / (1.0f + expf(-x)); }

__device__ __forceinline__ unsigned f2tf32(float x) {
    unsigned u;
    asm("cvt.rna.tf32.f32 %0, %1;" : "=r"(u) : "f"(x));
    return u;
}

__device__ __forceinline__ void mma8(float c[4], const unsigned a[4],
                                     unsigned b0, unsigned b1) {
    asm("mma.sync.aligned.m16n8k8.row.col.f32.tf32.tf32.f32 "
        "{%0,%1,%2,%3},{%4,%5,%6,%7},{%8,%9},{%0,%1,%2,%3};"
        : "+f"(c[0]), "+f"(c[1]), "+f"(c[2]), "+f"(c[3])
        : "r"(a[0]), "r"(a[1]), "r"(a[2]), "r"(a[3]), "r"(b0), "r"(b1));
}

__device__ __forceinline__ void cbar() {
    asm volatile("barrier.cluster.arrive.aligned;" ::: "memory");
    asm volatile("barrier.cluster.wait.aligned;" ::: "memory");
}

// JAX partitionable threefry bits: counter (0, i), key (0,1), bits = x0 ^ x1.
__device__ __forceinline__ float frand_sign(unsigned i) {
    const unsigned ks0 = 0u, ks1 = 1u, ks2 = 0x1BD11BDBu;
    unsigned x0 = 0u + ks0;
    unsigned x1 = i  + ks1;
#define QR4(RA,RB,RC,RD) \
    x0 += x1; x1 = __funnelshift_l(x1, x1, RA); x1 ^= x0; \
    x0 += x1; x1 = __funnelshift_l(x1, x1, RB); x1 ^= x0; \
    x0 += x1; x1 = __funnelshift_l(x1, x1, RC); x1 ^= x0; \
    x0 += x1; x1 = __funnelshift_l(x1, x1, RD); x1 ^= x0;
    QR4(13,15,26, 6)  x0 += ks1; x1 += ks2 + 1u;
    QR4(17,29,16,24)  x0 += ks2; x1 += ks0 + 2u;
    QR4(13,15,26, 6)  x0 += ks0; x1 += ks1 + 3u;
    QR4(17,29,16,24)  x0 += ks1; x1 += ks2 + 4u;
    QR4(13,15,26, 6)  x0 += ks2; x1 += ks0 + 5u;
#undef QR4
    return ((x0 ^ x1) & 0x80000000u) ? -1.0f : 1.0f;
}

// ---------------------------------------------------------------------------
// Weight packing (pair-interleaved, verbatim from R14).
// ---------------------------------------------------------------------------
__device__ void packSeg(unsigned* dst, const float* S1, int ld1,
                        const float* S2, int ld2, int ksplit,
                        int N, int KTl, int tid, int nth) {
    const int tot = (N / 8) * KTl * 32;
    for (int p = tid; p < tot; p += nth) {
        const int lane = p & 31, kt = (p >> 5) % KTl, nt = (p >> 5) / KTl;
        const int g = lane >> 2, t = lane & 3;
        const int n = nt * 8 + g;
        const int k0 = kt * 8 + t, k1 = k0 + 4;
        float v0 = (k0 < ksplit) ? S1[(size_t)n * ld1 + k0] : S2[(size_t)n * ld2 + (k0 - ksplit)];
        float v1 = (k1 < ksplit) ? S1[(size_t)n * ld1 + k1] : S2[(size_t)n * ld2 + (k1 - ksplit)];
        const int kp = kt >> 1, half = kt & 1;
        unsigned* q = dst + ((size_t)nt * KTl * 64 + (size_t)kp * 128 + lane * 4 + half * 2);
        q[0] = f2tf32(v0);
        q[1] = f2tf32(v1);
    }
}

__global__ void pack_kernel(const float* __restrict__ Wq,  const float* __restrict__ Wl1,
                            const float* __restrict__ Wl2, const float* __restrict__ Wih,
                            const float* __restrict__ Whh, const float* __restrict__ Wp1,
                            const float* __restrict__ Wp2) {
    const int tid = blockIdx.x * blockDim.x + threadIdx.x;
    const int nth = gridDim.x * blockDim.x;
    packSeg(g_wpack + OFF_WQ, Wq, 256, Wq, 256, 256, 512, KT_WQ, tid, nth);
    packSeg(g_wpack + OFF_L1, Wl1, 768, Wl1, 768, 768, 512, KT_L1, tid, nth);
    packSeg(g_wpack + OFF_L2, Wl2, 512, Wl2, 512, 512, 512, KT_L2, tid, nth);
    packSeg(g_wpack + OFF_RZ, Wih, 512, Whh, 512, 512, 1024, KT_RZ, tid, nth);
    packSeg(g_wpack + OFF_NI, Wih + 1024 * 512, 512, Wih, 512, 512, 512, KT_NI, tid, nth);
    packSeg(g_wpack + OFF_NH, Whh + 1024 * 512, 512, Whh, 512, 512, 512, KT_NH, tid, nth);
    packSeg(g_wpack + OFF_P1, Wp1, 512, Wp1, 512, 512, 512, KT_P1, tid, nth);
    packSeg(g_wpack + OFF_P2, Wp2, 512, Wp2, 512, 512, 256, KT_P2, tid, nth);
}

template<int STRIDE>
__device__ __forceinline__ void ldA(unsigned a[4], const unsigned* As, int kt, int g, int t) {
    const unsigned* p = As + g * STRIDE + kt * 8 + t;
    a[0] = p[0];
    a[1] = p[8 * STRIDE];
    a[2] = p[4];
    a[3] = p[8 * STRIDE + 4];
}

// Quarter GEMM, uint4 B with double-buffer prefetch (bn safely initialized).
template<int NT, int KTL>
__device__ __forceinline__ void gemmP(float C[][4], const unsigned* __restrict__ Bp,
                                      const int* tiles, const unsigned* As,
                                      int lane, int g, int t) {
    const unsigned* bptr[NT];
#pragma unroll
    for (int i = 0; i < NT; i++)
        bptr[i] = Bp + (size_t)tiles[i] * KTL * 64 + lane * 4;
    uint4 bc[NT];
#pragma unroll
    for (int i = 0; i < NT; i++) bc[i] = *(const uint4*)(bptr[i]);
#pragma unroll 2
    for (int kp = 0; kp < KTL / 2; kp++) {
        unsigned a0[4], a1[4];
        ldA<AST>(a0, As, 2 * kp, g, t);
        ldA<AST>(a1, As, 2 * kp + 1, g, t);
        uint4 bn[NT];
#pragma unroll
        for (int i = 0; i < NT; i++) bn[i] = bc[i];
        if (kp + 1 < KTL / 2) {
#pragma unroll
            for (int i = 0; i < NT; i++)
                bn[i] = *(const uint4*)(bptr[i] + (size_t)(kp + 1) * 128);
        }
#pragma unroll
        for (int i = 0; i < NT; i++) {
            mma8(C[i], a0, bc[i].x, bc[i].y);
            mma8(C[i], a1, bc[i].z, bc[i].w);
        }
#pragma unroll
        for (int i = 0; i < NT; i++) bc[i] = bn[i];
    }
}

#define ZC2(C, n) float C[n][4]; \
    _Pragma("unroll") for (int _i = 0; _i < n; _i++) { \
        C[_i][0] = 0.f; C[_i][1] = 0.f; C[_i][2] = 0.f; C[_i][3] = 0.f; }

// ---------------------------------------------------------------------------
// Persistent recurrence: 32 clusters x 4 CTAs x 512 threads, 32 rows/cluster.
// Barrier structure IDENTICAL to passing R14 (all full cbar).
// ---------------------------------------------------------------------------
__global__ void __launch_bounds__(512, 1) __cluster_dims__(4, 1, 1) recur_kernel(
    const float* __restrict__ Y0,
    const float* __restrict__ bq,
    const float* __restrict__ bl1, const float* __restrict__ bl2,
    const float* __restrict__ bih, const float* __restrict__ bhh,
    float* __restrict__ out)
{
    extern __shared__ unsigned smemU[];
    float* hFp = (float*)(smemU + HF_OFF);

    const int tid  = threadIdx.x;
    const int warp = tid >> 5, lane = tid & 31;
    const int g = lane >> 2, t = lane & 3;
    const int mt = warp >> 3, w8 = warp & 7;
    const int rank    = blockIdx.x & 3;
    const int rowBase = (blockIdx.x >> 2) * CROWS;
    const int r0 = mt * 16 + g, r1 = r0 + 8;
    const unsigned* Amt = smemU + mt * 16 * AST;

    unsigned sbase = (unsigned)__cvta_generic_to_shared(smemU);
    unsigned peerBase[4];
#pragma unroll
    for (int rk = 0; rk < 4; rk++)
        asm("mapa.shared::cluster.u32 %0, %1, %2;" : "=r"(peerBase[rk]) : "r"(sbase), "r"(rk));

    auto putA4 = [&](int row, int jc, unsigned u0, unsigned u1) {
        const unsigned off = 4u * (unsigned)(row * AST + jc);
        const unsigned long long pv = (unsigned long long)u0 | ((unsigned long long)u1 << 32);
#pragma unroll
        for (int rk = 0; rk < 4; rk++)
            asm volatile("st.shared::cluster.u64 [%0], %1;"
                         :: "r"(peerBase[rk] + off), "l"(pv) : "memory");
    };

    const int T1 = 16 * rank + 2 * w8;
    int tl2[2] = {T1, T1 + 1};
    int tl4[4] = {T1, T1 + 1, 64 + T1, 64 + T1 + 1};
    const int jgA = 128 * rank + 2 * w8 * 8 + 2 * t;
    const int jlA = 2 * w8 * 8 + 2 * t;

    // ---- x0 = tanh(Y0[0] @ Wq.T + bq) ----
    for (int i = tid; i < CROWS * 256; i += 512) {
        const int r = i >> 8, cl = i & 255;
        smemU[r * AST + 1024 + cl] = f2tf32(Y0[(size_t)(rowBase + r) * NYY + cl]);
    }
    cbar();
    {
        ZC2(Cq, 2);
        gemmP<2, KT_WQ>(Cq, g_wpack + OFF_WQ, tl2, Amt + 1024, lane, g, t);
#pragma unroll
        for (int i = 0; i < 2; i++) {
            const int jg = jgA + i * 8, jl = jlA + i * 8;
            const float h00 = tanhf(Cq[i][0] + bq[jg]);
            const float h01 = tanhf(Cq[i][1] + bq[jg + 1]);
            const float h10 = tanhf(Cq[i][2] + bq[jg]);
            const float h11 = tanhf(Cq[i][3] + bq[jg + 1]);
            hFp[r0 * 132 + jl] = h00; hFp[r0 * 132 + jl + 1] = h01;
            hFp[r1 * 132 + jl] = h10; hFp[r1 * 132 + jl + 1] = h11;
            putA4(r0, 512 + jg, f2tf32(h00), f2tf32(h01));
            putA4(r1, 512 + jg, f2tf32(h10), f2tf32(h11));
            *(float2*)(out + (size_t)(rowBase + r0) * NXX + jg) = make_float2(h00, h01);
            *(float2*)(out + (size_t)(rowBase + r1) * NXX + jg) = make_float2(h10, h11);
        }
    }
    cbar();
    // preload y for step 0 (= Y0[1]); y region is CTA-local, Wq reads done (cbar)
    for (int i = tid; i < CROWS * 256; i += 512) {
        const int r = i >> 8, cl = i & 255;
        smemU[r * AST + 1024 + cl] =
            f2tf32(Y0[((size_t)1 * NB + rowBase + r) * NYY + cl]);
    }
    __syncthreads();

    // ---- 160 sequential steps ----
    for (int tstep = 0; tstep < NWUP + NHR; tstep++) {
        if (tstep < NWUP) {
            // l1 = tanh([h|y] @ Wl1.T + bl1) -> ACT[0,512) of all ranks
            {
                ZC2(C, 2);
                gemmP<2, KT_L1>(C, g_wpack + OFF_L1, tl2, Amt + 512, lane, g, t);
#pragma unroll
                for (int i = 0; i < 2; i++) {
                    const int jg = jgA + i * 8;
                    putA4(r0, jg, f2tf32(tanhf(C[i][0] + bl1[jg])),
                                  f2tf32(tanhf(C[i][1] + bl1[jg + 1])));
                    putA4(r1, jg, f2tf32(tanhf(C[i][2] + bl1[jg])),
                                  f2tf32(tanhf(C[i][3] + bl1[jg + 1])));
                }
            }
            cbar();   // B1: l1 visible; all local y reads done (full barrier)

            // issue next-step y LDGs into registers (hide behind l2 GEMM)
            const bool pf = (tstep + 2 <= NWUP);
            float yreg[16];
            if (pf) {
                const float* ysrc = Y0 + ((size_t)(tstep + 2) * NB + rowBase) * NYY;
#pragma unroll
                for (int k = 0; k < 16; k++) {
                    const int idx = tid + 512 * k;
                    yreg[k] = ysrc[(size_t)(idx >> 8) * NYY + (idx & 255)];
                }
            }

            // logit = l1 @ Wl2.T + bl2 -> gmem ; w = tanh(0.5*logit)
            {
                ZC2(C, 2);
                gemmP<2, KT_L2>(C, g_wpack + OFF_L2, tl2, Amt, lane, g, t);
                cbar();   // B2: l1 consumed cluster-wide before overwrite with w
                float* lb = out + L_OFF + ((size_t)tstep * NB + rowBase) * NWW;
#pragma unroll
                for (int i = 0; i < 2; i++) {
                    const int jg = jgA + i * 8;
                    const float lg00 = C[i][0] + bl2[jg];
                    const float lg01 = C[i][1] + bl2[jg + 1];
                    const float lg10 = C[i][2] + bl2[jg];
                    const float lg11 = C[i][3] + bl2[jg + 1];
                    *(float2*)(lb + (size_t)r0 * NWW + jg) = make_float2(lg00, lg01);
                    *(float2*)(lb + (size_t)r1 * NWW + jg) = make_float2(lg10, lg11);
                    putA4(r0, jg, f2tf32(tanhf(0.5f * lg00)), f2tf32(tanhf(0.5f * lg01)));
                    putA4(r1, jg, f2tf32(tanhf(0.5f * lg10)), f2tf32(tanhf(0.5f * lg11)));
                }
            }
            // store prefetched y (local-only region; ordered by cbar B3 below)
            if (pf) {
#pragma unroll
                for (int k = 0; k < 16; k++) {
                    const int idx = tid + 512 * k;
                    smemU[(idx >> 8) * AST + 1024 + (idx & 255)] = f2tf32(yreg[k]);
                }
            }
            cbar();   // B3: w (and local y) ready everywhere
        } else {
            // free-run: w generated at step top (R14 structure)
            const unsigned tf = (unsigned)(tstep - NWUP);
            for (int i = tid; i < CROWS * 512; i += 512) {
                const int r = i >> 9, j = i & 511;
                const unsigned idx = (((unsigned)tf * NB + (unsigned)(rowBase + r)) << 9) + (unsigned)j;
                smemU[r * AST + j] = __float_as_uint(frand_sign(idx));
            }
            __syncthreads();
        }

        // ---- merged GRU GEMMs: rz + ni + nh in one loop ----
        ZC2(Crz, 4); ZC2(Cni, 2); ZC2(Cnh, 2);
        {
            const unsigned* brz[4];
            const unsigned* bni[2];
            const unsigned* bnh[2];
#pragma unroll
            for (int i = 0; i < 4; i++)
                brz[i] = g_wpack + OFF_RZ + (size_t)tl4[i] * KT_RZ * 64 + lane * 4;
#pragma unroll
            for (int i = 0; i < 2; i++) {
                bni[i] = g_wpack + OFF_NI + (size_t)tl2[i] * KT_NI * 64 + lane * 4;
                bnh[i] = g_wpack + OFF_NH + (size_t)tl2[i] * KT_NH * 64 + lane * 4;
            }
#pragma unroll 2
            for (int kp = 0; kp < 32; kp++) {
                unsigned aw0[4], aw1[4], ah0[4], ah1[4];
                ldA<AST>(aw0, Amt, 2 * kp, g, t);
                ldA<AST>(aw1, Amt, 2 * kp + 1, g, t);
                ldA<AST>(ah0, Amt + 512, 2 * kp, g, t);
                ldA<AST>(ah1, Amt + 512, 2 * kp + 1, g, t);
#pragma unroll
                for (int i = 0; i < 4; i++) {
                    uint4 b = *(const uint4*)(brz[i] + (size_t)kp * 128);
                    mma8(Crz[i], aw0, b.x, b.y);
                    mma8(Crz[i], aw1, b.z, b.w);
                    uint4 b2 = *(const uint4*)(brz[i] + (size_t)(kp + 32) * 128);
                    mma8(Crz[i], ah0, b2.x, b2.y);
                    mma8(Crz[i], ah1, b2.z, b2.w);
                }
#pragma unroll
                for (int i = 0; i < 2; i++) {
                    uint4 b = *(const uint4*)(bni[i] + (size_t)kp * 128);
                    mma8(Cni[i], aw0, b.x, b.y);
                    mma8(Cni[i], aw1, b.z, b.w);
                    uint4 c = *(const uint4*)(bnh[i] + (size_t)kp * 128);
                    mma8(Cnh[i], ah0, c.x, c.y);
                    mma8(Cnh[i], ah1, c.z, c.w);
                }
            }
        }
        cbar();   // B4: all reads of h/w done cluster-wide

        // ---- h update (R14 structure) ----
        float* xb = out + ((size_t)(tstep + 1) * NB + rowBase) * NXX;
#pragma unroll
        for (int i = 0; i < 2; i++) {
            const int jg0 = jgA + i * 8, jl0 = jlA + i * 8;
            float hva[2], hvb[2];
#pragma unroll
            for (int cc = 0; cc < 2; cc++) {
                const int jg = jg0 + cc;
                const float br  = bih[jg] + bhh[jg];
                const float bz  = bih[jg + 512] + bhh[jg + 512];
                const float bi3 = bih[jg + 1024], bh3 = bhh[jg + 1024];
                {
                    const float rv = sigm(Crz[i][cc] + br);
                    const float zv = sigm(Crz[2 + i][cc] + bz);
                    const float nv = tanhf(Cni[i][cc] + bi3 + rv * (Cnh[i][cc] + bh3));
                    const float ho = hFp[r0 * 132 + jl0 + cc];
                    const float hv = (1.0f - zv) * nv + zv * ho;
                    hFp[r0 * 132 + jl0 + cc] = hv;
                    hva[cc] = hv;
                }
                {
                    const float rv = sigm(Crz[i][2 + cc] + br);
                    const float zv = sigm(Crz[2 + i][2 + cc] + bz);
                    const float nv = tanhf(Cni[i][2 + cc] + bi3 + rv * (Cnh[i][2 + cc] + bh3));
                    const float ho = hFp[r1 * 132 + jl0 + cc];
                    const float hv = (1.0f - zv) * nv + zv * ho;
                    hFp[r1 * 132 + jl0 + cc] = hv;
                    hvb[cc] = hv;
                }
            }
            putA4(r0, 512 + jg0, f2tf32(hva[0]), f2tf32(hva[1]));
            putA4(r1, 512 + jg0, f2tf32(hvb[0]), f2tf32(hvb[1]));
            *(float2*)(xb + (size_t)r0 * NXX + jg0) = make_float2(hva[0], hva[1]);
            *(float2*)(xb + (size_t)r1 * NXX + jg0) = make_float2(hvb[0], hvb[1]);
        }
        cbar();   // B5: h ready everywhere
    }
}

// ---------------------------------------------------------------------------
// proj (verbatim from R14)
// ---------------------------------------------------------------------------
__global__ void __launch_bounds__(512, 1) proj_kernel(
    const float* __restrict__ bp1, const float* __restrict__ bp2,
    float* __restrict__ out)
{
    extern __shared__ unsigned XA[];
    const int tid = threadIdx.x, warp = tid >> 5, lane = tid & 31;
    const int g = lane >> 2, t = lane & 3;
    const size_t rowBase = (size_t)blockIdx.x * PROJ_ROWS;

    for (int i = tid; i < PROJ_ROWS * 512; i += 512) {
        const int r = i >> 9, cl = i & 511;
        XA[r * 516 + cl] = f2tf32(out[(rowBase + r) * NXX + cl]);
    }
    __syncthreads();

    float C[4][4][4];
#pragma unroll
    for (int m = 0; m < 4; m++)
#pragma unroll
        for (int i = 0; i < 4; i++) { C[m][i][0]=0.f; C[m][i][1]=0.f; C[m][i][2]=0.f; C[m][i][3]=0.f; }
    {
        const unsigned* bbase = g_wpack + OFF_P1 + (size_t)(4 * warp) * KT_P1 * 64 + lane * 4;
#pragma unroll 1
        for (int kp = 0; kp < KT_P1 / 2; kp++) {
            unsigned a0[4][4], a1[4][4];
#pragma unroll
            for (int m = 0; m < 4; m++) {
                ldA<516>(a0[m], XA + m * 16 * 516, 2 * kp, g, t);
                ldA<516>(a1[m], XA + m * 16 * 516, 2 * kp + 1, g, t);
            }
#pragma unroll
            for (int i = 0; i < 4; i++) {
                uint4 b = *(const uint4*)(bbase + (size_t)i * KT_P1 * 64 + (size_t)kp * 128);
#pragma unroll
                for (int m = 0; m < 4; m++) {
                    mma8(C[m][i], a0[m], b.x, b.y);
                    mma8(C[m][i], a1[m], b.z, b.w);
                }
            }
        }
    }
    __syncthreads();
#pragma unroll
    for (int m = 0; m < 4; m++)
#pragma unroll
        for (int i = 0; i < 4; i++) {
            const int j0 = 32 * warp + i * 8 + 2 * t;
            XA[(m * 16 + g) * 516 + j0]         = f2tf32(tanhf(C[m][i][0] + bp1[j0]));
            XA[(m * 16 + g) * 516 + j0 + 1]     = f2tf32(tanhf(C[m][i][1] + bp1[j0 + 1]));
            XA[(m * 16 + g + 8) * 516 + j0]     = f2tf32(tanhf(C[m][i][2] + bp1[j0]));
            XA[(m * 16 + g + 8) * 516 + j0 + 1] = f2tf32(tanhf(C[m][i][3] + bp1[j0 + 1]));
        }
    __syncthreads();

    float C2[4][2][4];
#pragma unroll
    for (int m = 0; m < 4; m++)
#pragma unroll
        for (int i = 0; i < 2; i++) { C2[m][i][0]=0.f; C2[m][i][1]=0.f; C2[m][i][2]=0.f; C2[m][i][3]=0.f; }
    {
        const unsigned* bbase = g_wpack + OFF_P2 + (size_t)(2 * warp) * KT_P2 * 64 + lane * 4;
#pragma unroll 1
        for (int kp = 0; kp < KT_P2 / 2; kp++) {
            unsigned a0[4][4], a1[4][4];
#pragma unroll
            for (int m = 0; m < 4; m++) {
                ldA<516>(a0[m], XA + m * 16 * 516, 2 * kp, g, t);
                ldA<516>(a1[m], XA + m * 16 * 516, 2 * kp + 1, g, t);
            }
#pragma unroll
            for (int i = 0; i < 2; i++) {
                uint4 b = *(const uint4*)(bbase + (size_t)i * KT_P2 * 64 + (size_t)kp * 128);
#pragma unroll
                for (int m = 0; m < 4; m++) {
                    mma8(C2[m][i], a0[m], b.x, b.y);
                    mma8(C2[m][i], a1[m], b.z, b.w);
                }
            }
        }
    }
#pragma unroll
    for (int m = 0; m < 4; m++)
#pragma unroll
        for (int i = 0; i < 2; i++) {
            const int j0 = 16 * warp + i * 8 + 2 * t;
            float* y0 = out + Y_OFF + (rowBase + m * 16 + g) * NYY;
            float* y1 = out + Y_OFF + (rowBase + m * 16 + g + 8) * NYY;
            y0[j0]     = C2[m][i][0] + bp2[j0];
            y0[j0 + 1] = C2[m][i][1] + bp2[j0 + 1];
            y1[j0]     = C2[m][i][2] + bp2[j0];
            y1[j0 + 1] = C2[m][i][3] + bp2[j0 + 1];
        }
}

extern "C" void kernel_launch(void* const* d_in, const int* in_sizes, int n_in,
                              void* d_out, int out_size) {
    int off = (n_in >= 16 && in_sizes[1] == 1) ? 2 : 1;
    const float* Y0  = (const float*)d_in[0];
    const float* Wq  = (const float*)d_in[off + 0];
    const float* bq  = (const float*)d_in[off + 1];
    const float* Wp1 = (const float*)d_in[off + 2];
    const float* bp1 = (const float*)d_in[off + 3];
    const float* Wp2 = (const float*)d_in[off + 4];
    const float* bp2 = (const float*)d_in[off + 5];
    const float* Wl1 = (const float*)d_in[off + 6];
    const float* bl1 = (const float*)d_in[off + 7];
    const float* Wl2 = (const float*)d_in[off + 8];
    const float* bl2 = (const float*)d_in[off + 9];
    const float* Wih = (const float*)d_in[off + 10];
    const float* Whh = (const float*)d_in[off + 11];
    const float* bih = (const float*)d_in[off + 12];
    const float* bhh = (const float*)d_in[off + 13];
    float* out = (float*)d_out;

    cudaFuncSetAttribute(recur_kernel, cudaFuncAttributeMaxDynamicSharedMemorySize,
                         SMEM_UNITS * 4);
    cudaFuncSetAttribute(proj_kernel, cudaFuncAttributeMaxDynamicSharedMemorySize,
                         PROJ_SMEM_UNITS * 4);

    pack_kernel<<<128, 256>>>(Wq, Wl1, Wl2, Wih, Whh, Wp1, Wp2);
    recur_kernel<<<NCTA, 512, SMEM_UNITS * 4>>>(Y0, bq, bl1, bl2, bih, bhh, out);
    proj_kernel<<<(TT * NB) / PROJ_ROWS, 512, PROJ_SMEM_UNITS * 4>>>(bp1, bp2, out);
}

// round 17
// speedup vs baseline: 1.0288x; 1.0288x over previous
#include <cuda_runtime.h>
#include <math.h>

#define NXX   512
#define NWW   512
#define NYY   256
#define NWUP  128
#define NB    1024
#define NHR   32
#define TT    (NWUP + 1 + NHR)          // 161

#define X_SIZE   ((size_t)TT * NB * NXX)
#define L_OFF    (X_SIZE)
#define L_SIZE   ((size_t)NWUP * NB * NWW)
#define Y_OFF    (L_OFF + L_SIZE)

#define CROWS 32
#define NCTA  128

#define RAND_N   (NHR * NB * NWW)       // 16,777,216

// ---- packed tf32 weight buffers (pair-interleaved B-fragment order) ----
#define KT_WQ 32
#define KT_L1 96
#define KT_L2 64
#define KT_RZ 128
#define KT_NI 64
#define KT_NH 64
#define KT_P1 64
#define KT_P2 64
#define OFF_WQ 0
#define SZ_WQ  (64 * KT_WQ * 64)
#define OFF_L1 (OFF_WQ + SZ_WQ)
#define SZ_L1  (64 * KT_L1 * 64)
#define OFF_L2 (OFF_L1 + SZ_L1)
#define SZ_L2  (64 * KT_L2 * 64)
#define OFF_RZ (OFF_L2 + SZ_L2)
#define SZ_RZ  (128 * KT_RZ * 64)
#define OFF_NI (OFF_RZ + SZ_RZ)
#define SZ_NI  (64 * KT_NI * 64)
#define OFF_NH (OFF_NI + SZ_NI)
#define SZ_NH  (64 * KT_NH * 64)
#define OFF_P1 (OFF_NH + SZ_NH)
#define SZ_P1  (64 * KT_P1 * 64)
#define OFF_P2 (OFF_P1 + SZ_P1)
#define SZ_P2  (32 * KT_P2 * 64)
#define WPACK_TOTAL (OFF_P2 + SZ_P2)

__device__ unsigned g_wpack[WPACK_TOTAL];
__device__ float    g_wrand[RAND_N];

// ---- recurrence smem: ACT [32][1284] tf32 (w/l1:0-511, h:512-1023, y:1024-1279)
//      + HF [32][132] fp32 ----
#define AST     1284
#define HF_OFF  (CROWS * AST)
#define SMEM_UNITS (HF_OFF + CROWS * 132)

#define PROJ_ROWS 64
#define PROJ_SMEM_UNITS (PROJ_ROWS * 516)

__device__ __forceinline__ float sigm(float x) { return 1.0f / (1.0f + expf(-x)); }

__device__ __forceinline__ unsigned f2tf32(float x) {
    unsigned u;
    asm("cvt.rna.tf32.f32 %0, %1;" : "=r"(u) : "f"(x));
    return u;
}

__device__ __forceinline__ void mma8(float c[4], const unsigned a[4],
                                     unsigned b0, unsigned b1) {
    asm("mma.sync.aligned.m16n8k8.row.col.f32.tf32.tf32.f32 "
        "{%0,%1,%2,%3},{%4,%5,%6,%7},{%8,%9},{%0,%1,%2,%3};"
        : "+f"(c[0]), "+f"(c[1]), "+f"(c[2]), "+f"(c[3])
        : "r"(a[0]), "r"(a[1]), "r"(a[2]), "r"(a[3]), "r"(b0), "r"(b1));
}

__device__ __forceinline__ void cbar() {
    asm volatile("barrier.cluster.arrive.aligned;" ::: "memory");
    asm volatile("barrier.cluster.wait.aligned;" ::: "memory");
}

// JAX partitionable threefry bits: counter (0, i), key (0,1), bits = x0 ^ x1.
__device__ __forceinline__ float frand_sign(unsigned i) {
    const unsigned ks0 = 0u, ks1 = 1u, ks2 = 0x1BD11BDBu;
    unsigned x0 = 0u + ks0;
    unsigned x1 = i  + ks1;
#define QR4(RA,RB,RC,RD) \
    x0 += x1; x1 = __funnelshift_l(x1, x1, RA); x1 ^= x0; \
    x0 += x1; x1 = __funnelshift_l(x1, x1, RB); x1 ^= x0; \
    x0 += x1; x1 = __funnelshift_l(x1, x1, RC); x1 ^= x0; \
    x0 += x1; x1 = __funnelshift_l(x1, x1, RD); x1 ^= x0;
    QR4(13,15,26, 6)  x0 += ks1; x1 += ks2 + 1u;
    QR4(17,29,16,24)  x0 += ks2; x1 += ks0 + 2u;
    QR4(13,15,26, 6)  x0 += ks0; x1 += ks1 + 3u;
    QR4(17,29,16,24)  x0 += ks1; x1 += ks2 + 4u;
    QR4(13,15,26, 6)  x0 += ks2; x1 += ks0 + 5u;
#undef QR4
    return ((x0 ^ x1) & 0x80000000u) ? -1.0f : 1.0f;
}

// precompute all free-run signs (runs once, off the critical path)
__global__ void rand_kernel() {
    for (unsigned i = blockIdx.x * blockDim.x + threadIdx.x; i < (unsigned)RAND_N;
         i += gridDim.x * blockDim.x)
        g_wrand[i] = frand_sign(i);
}

// ---------------------------------------------------------------------------
// Weight packing (pair-interleaved, verbatim from R14).
// ---------------------------------------------------------------------------
__device__ void packSeg(unsigned* dst, const float* S1, int ld1,
                        const float* S2, int ld2, int ksplit,
                        int N, int KTl, int tid, int nth) {
    const int tot = (N / 8) * KTl * 32;
    for (int p = tid; p < tot; p += nth) {
        const int lane = p & 31, kt = (p >> 5) % KTl, nt = (p >> 5) / KTl;
        const int g = lane >> 2, t = lane & 3;
        const int n = nt * 8 + g;
        const int k0 = kt * 8 + t, k1 = k0 + 4;
        float v0 = (k0 < ksplit) ? S1[(size_t)n * ld1 + k0] : S2[(size_t)n * ld2 + (k0 - ksplit)];
        float v1 = (k1 < ksplit) ? S1[(size_t)n * ld1 + k1] : S2[(size_t)n * ld2 + (k1 - ksplit)];
        const int kp = kt >> 1, half = kt & 1;
        unsigned* q = dst + ((size_t)nt * KTl * 64 + (size_t)kp * 128 + lane * 4 + half * 2);
        q[0] = f2tf32(v0);
        q[1] = f2tf32(v1);
    }
}

__global__ void pack_kernel(const float* __restrict__ Wq,  const float* __restrict__ Wl1,
                            const float* __restrict__ Wl2, const float* __restrict__ Wih,
                            const float* __restrict__ Whh, const float* __restrict__ Wp1,
                            const float* __restrict__ Wp2) {
    const int tid = blockIdx.x * blockDim.x + threadIdx.x;
    const int nth = gridDim.x * blockDim.x;
    packSeg(g_wpack + OFF_WQ, Wq, 256, Wq, 256, 256, 512, KT_WQ, tid, nth);
    packSeg(g_wpack + OFF_L1, Wl1, 768, Wl1, 768, 768, 512, KT_L1, tid, nth);
    packSeg(g_wpack + OFF_L2, Wl2, 512, Wl2, 512, 512, 512, KT_L2, tid, nth);
    packSeg(g_wpack + OFF_RZ, Wih, 512, Whh, 512, 512, 1024, KT_RZ, tid, nth);
    packSeg(g_wpack + OFF_NI, Wih + 1024 * 512, 512, Wih, 512, 512, 512, KT_NI, tid, nth);
    packSeg(g_wpack + OFF_NH, Whh + 1024 * 512, 512, Whh, 512, 512, 512, KT_NH, tid, nth);
    packSeg(g_wpack + OFF_P1, Wp1, 512, Wp1, 512, 512, 512, KT_P1, tid, nth);
    packSeg(g_wpack + OFF_P2, Wp2, 512, Wp2, 512, 512, 256, KT_P2, tid, nth);
}

template<int STRIDE>
__device__ __forceinline__ void ldA(unsigned a[4], const unsigned* As, int kt, int g, int t) {
    const unsigned* p = As + g * STRIDE + kt * 8 + t;
    a[0] = p[0];
    a[1] = p[8 * STRIDE];
    a[2] = p[4];
    a[3] = p[8 * STRIDE + 4];
}

// Quarter GEMM, uint4 B (R14 form — no double buffering).
template<int NT, int KTL>
__device__ __forceinline__ void gemmP(float C[][4], const unsigned* __restrict__ Bp,
                                      const int* tiles, const unsigned* As,
                                      int lane, int g, int t) {
    const unsigned* bptr[NT];
#pragma unroll
    for (int i = 0; i < NT; i++)
        bptr[i] = Bp + (size_t)tiles[i] * KTL * 64 + lane * 4;
#pragma unroll 2
    for (int kp = 0; kp < KTL / 2; kp++) {
        unsigned a0[4], a1[4];
        ldA<AST>(a0, As, 2 * kp, g, t);
        ldA<AST>(a1, As, 2 * kp + 1, g, t);
#pragma unroll
        for (int i = 0; i < NT; i++) {
            uint4 b = *(const uint4*)(bptr[i] + (size_t)kp * 128);
            mma8(C[i], a0, b.x, b.y);
            mma8(C[i], a1, b.z, b.w);
        }
    }
}

#define ZC2(C, n) float C[n][4]; \
    _Pragma("unroll") for (int _i = 0; _i < n; _i++) { \
        C[_i][0] = 0.f; C[_i][1] = 0.f; C[_i][2] = 0.f; C[_i][3] = 0.f; }

// ---------------------------------------------------------------------------
// Persistent recurrence: 32 clusters x 4 CTAs x 512 threads, 32 rows/cluster.
// Structure IDENTICAL to passing R14; only free-run w comes from g_wrand.
// ---------------------------------------------------------------------------
__global__ void __launch_bounds__(512, 1) __cluster_dims__(4, 1, 1) recur_kernel(
    const float* __restrict__ Y0,
    const float* __restrict__ bq,
    const float* __restrict__ bl1, const float* __restrict__ bl2,
    const float* __restrict__ bih, const float* __restrict__ bhh,
    float* __restrict__ out)
{
    extern __shared__ unsigned smemU[];
    float* hFp = (float*)(smemU + HF_OFF);

    const int tid  = threadIdx.x;
    const int warp = tid >> 5, lane = tid & 31;
    const int g = lane >> 2, t = lane & 3;
    const int mt = warp >> 3, w8 = warp & 7;
    const int rank    = blockIdx.x & 3;
    const int rowBase = (blockIdx.x >> 2) * CROWS;
    const int r0 = mt * 16 + g, r1 = r0 + 8;
    const unsigned* Amt = smemU + mt * 16 * AST;

    unsigned sbase = (unsigned)__cvta_generic_to_shared(smemU);
    unsigned peerBase[4];
#pragma unroll
    for (int rk = 0; rk < 4; rk++)
        asm("mapa.shared::cluster.u32 %0, %1, %2;" : "=r"(peerBase[rk]) : "r"(sbase), "r"(rk));

    auto putA4 = [&](int row, int jc, unsigned u0, unsigned u1) {
        const unsigned off = 4u * (unsigned)(row * AST + jc);
        const unsigned long long pv = (unsigned long long)u0 | ((unsigned long long)u1 << 32);
#pragma unroll
        for (int rk = 0; rk < 4; rk++)
            asm volatile("st.shared::cluster.u64 [%0], %1;"
                         :: "r"(peerBase[rk] + off), "l"(pv) : "memory");
    };

    const int T1 = 16 * rank + 2 * w8;
    int tl2[2] = {T1, T1 + 1};
    int tl4[4] = {T1, T1 + 1, 64 + T1, 64 + T1 + 1};
    const int jgA = 128 * rank + 2 * w8 * 8 + 2 * t;
    const int jlA = 2 * w8 * 8 + 2 * t;

    // ---- x0 = tanh(Y0[0] @ Wq.T + bq) ----
    for (int i = tid; i < CROWS * 256; i += 512) {
        const int r = i >> 8, cl = i & 255;
        smemU[r * AST + 1024 + cl] = f2tf32(Y0[(size_t)(rowBase + r) * NYY + cl]);
    }
    cbar();
    {
        ZC2(Cq, 2);
        gemmP<2, KT_WQ>(Cq, g_wpack + OFF_WQ, tl2, Amt + 1024, lane, g, t);
#pragma unroll
        for (int i = 0; i < 2; i++) {
            const int jg = jgA + i * 8, jl = jlA + i * 8;
            const float h00 = tanhf(Cq[i][0] + bq[jg]);
            const float h01 = tanhf(Cq[i][1] + bq[jg + 1]);
            const float h10 = tanhf(Cq[i][2] + bq[jg]);
            const float h11 = tanhf(Cq[i][3] + bq[jg + 1]);
            hFp[r0 * 132 + jl] = h00; hFp[r0 * 132 + jl + 1] = h01;
            hFp[r1 * 132 + jl] = h10; hFp[r1 * 132 + jl + 1] = h11;
            putA4(r0, 512 + jg, f2tf32(h00), f2tf32(h01));
            putA4(r1, 512 + jg, f2tf32(h10), f2tf32(h11));
            *(float2*)(out + (size_t)(rowBase + r0) * NXX + jg) = make_float2(h00, h01);
            *(float2*)(out + (size_t)(rowBase + r1) * NXX + jg) = make_float2(h10, h11);
        }
    }
    cbar();

    // ---- 160 sequential steps ----
    for (int tstep = 0; tstep < NWUP + NHR; tstep++) {
        if (tstep < NWUP) {
            // y = Y0[t+1] -> local ACT.y
            for (int i = tid; i < CROWS * 256; i += 512) {
                const int r = i >> 8, cl = i & 255;
                smemU[r * AST + 1024 + cl] =
                    f2tf32(Y0[((size_t)(tstep + 1) * NB + rowBase + r) * NYY + cl]);
            }
            __syncthreads();

            // l1 = tanh([h|y] @ Wl1.T + bl1) -> ACT[0,512) of all ranks
            {
                ZC2(C, 2);
                gemmP<2, KT_L1>(C, g_wpack + OFF_L1, tl2, Amt + 512, lane, g, t);
#pragma unroll
                for (int i = 0; i < 2; i++) {
                    const int jg = jgA + i * 8;
                    putA4(r0, jg, f2tf32(tanhf(C[i][0] + bl1[jg])),
                                  f2tf32(tanhf(C[i][1] + bl1[jg + 1])));
                    putA4(r1, jg, f2tf32(tanhf(C[i][2] + bl1[jg])),
                                  f2tf32(tanhf(C[i][3] + bl1[jg + 1])));
                }
            }
            cbar();   // B1: l1 complete cluster-wide

            // logit = l1 @ Wl2.T + bl2 -> gmem ; w = tanh(0.5*logit)
            {
                ZC2(C, 2);
                gemmP<2, KT_L2>(C, g_wpack + OFF_L2, tl2, Amt, lane, g, t);
                cbar();   // B2: l1 consumed before overwrite with w
                float* lb = out + L_OFF + ((size_t)tstep * NB + rowBase) * NWW;
#pragma unroll
                for (int i = 0; i < 2; i++) {
                    const int jg = jgA + i * 8;
                    const float lg00 = C[i][0] + bl2[jg];
                    const float lg01 = C[i][1] + bl2[jg + 1];
                    const float lg10 = C[i][2] + bl2[jg];
                    const float lg11 = C[i][3] + bl2[jg + 1];
                    *(float2*)(lb + (size_t)r0 * NWW + jg) = make_float2(lg00, lg01);
                    *(float2*)(lb + (size_t)r1 * NWW + jg) = make_float2(lg10, lg11);
                    putA4(r0, jg, f2tf32(tanhf(0.5f * lg00)), f2tf32(tanhf(0.5f * lg01)));
                    putA4(r1, jg, f2tf32(tanhf(0.5f * lg10)), f2tf32(tanhf(0.5f * lg11)));
                }
            }
            cbar();   // B3: w ready everywhere
        } else {
            // free-run: load precomputed signs (CTA-local region)
            const unsigned tf = (unsigned)(tstep - NWUP);
            const float* ws = g_wrand + ((size_t)tf * NB + rowBase) * NWW;
            for (int i = tid; i < CROWS * 128; i += 512) {
                const int r = i >> 7, j4 = (i & 127) * 4;
                float4 v = *(const float4*)(ws + (size_t)r * NWW + j4);
                unsigned* d = smemU + r * AST + j4;
                d[0] = __float_as_uint(v.x);
                d[1] = __float_as_uint(v.y);
                d[2] = __float_as_uint(v.z);
                d[3] = __float_as_uint(v.w);
            }
            __syncthreads();
        }

        // ---- merged GRU GEMMs: rz + ni + nh in one loop ----
        ZC2(Crz, 4); ZC2(Cni, 2); ZC2(Cnh, 2);
        {
            const unsigned* brz[4];
            const unsigned* bni[2];
            const unsigned* bnh[2];
#pragma unroll
            for (int i = 0; i < 4; i++)
                brz[i] = g_wpack + OFF_RZ + (size_t)tl4[i] * KT_RZ * 64 + lane * 4;
#pragma unroll
            for (int i = 0; i < 2; i++) {
                bni[i] = g_wpack + OFF_NI + (size_t)tl2[i] * KT_NI * 64 + lane * 4;
                bnh[i] = g_wpack + OFF_NH + (size_t)tl2[i] * KT_NH * 64 + lane * 4;
            }
#pragma unroll 2
            for (int kp = 0; kp < 32; kp++) {
                unsigned aw0[4], aw1[4], ah0[4], ah1[4];
                ldA<AST>(aw0, Amt, 2 * kp, g, t);
                ldA<AST>(aw1, Amt, 2 * kp + 1, g, t);
                ldA<AST>(ah0, Amt + 512, 2 * kp, g, t);
                ldA<AST>(ah1, Amt + 512, 2 * kp + 1, g, t);
#pragma unroll
                for (int i = 0; i < 4; i++) {
                    uint4 b = *(const uint4*)(brz[i] + (size_t)kp * 128);
                    mma8(Crz[i], aw0, b.x, b.y);
                    mma8(Crz[i], aw1, b.z, b.w);
                    uint4 b2 = *(const uint4*)(brz[i] + (size_t)(kp + 32) * 128);
                    mma8(Crz[i], ah0, b2.x, b2.y);
                    mma8(Crz[i], ah1, b2.z, b2.w);
                }
#pragma unroll
                for (int i = 0; i < 2; i++) {
                    uint4 b = *(const uint4*)(bni[i] + (size_t)kp * 128);
                    mma8(Cni[i], aw0, b.x, b.y);
                    mma8(Cni[i], aw1, b.z, b.w);
                    uint4 c = *(const uint4*)(bnh[i] + (size_t)kp * 128);
                    mma8(Cnh[i], ah0, c.x, c.y);
                    mma8(Cnh[i], ah1, c.z, c.w);
                }
            }
        }
        cbar();   // B4: all reads of h/w done cluster-wide

        // ---- h update ----
        float* xb = out + ((size_t)(tstep + 1) * NB + rowBase) * NXX;
#pragma unroll
        for (int i = 0; i < 2; i++) {
            const int jg0 = jgA + i * 8, jl0 = jlA + i * 8;
            float hva[2], hvb[2];
#pragma unroll
            for (int cc = 0; cc < 2; cc++) {
                const int jg = jg0 + cc;
                const float br  = bih[jg] + bhh[jg];
                const float bz  = bih[jg + 512] + bhh[jg + 512];
                const float bi3 = bih[jg + 1024], bh3 = bhh[jg + 1024];
                {
                    const float rv = sigm(Crz[i][cc] + br);
                    const float zv = sigm(Crz[2 + i][cc] + bz);
                    const float nv = tanhf(Cni[i][cc] + bi3 + rv * (Cnh[i][cc] + bh3));
                    const float ho = hFp[r0 * 132 + jl0 + cc];
                    const float hv = (1.0f - zv) * nv + zv * ho;
                    hFp[r0 * 132 + jl0 + cc] = hv;
                    hva[cc] = hv;
                }
                {
                    const float rv = sigm(Crz[i][2 + cc] + br);
                    const float zv = sigm(Crz[2 + i][2 + cc] + bz);
                    const float nv = tanhf(Cni[i][2 + cc] + bi3 + rv * (Cnh[i][2 + cc] + bh3));
                    const float ho = hFp[r1 * 132 + jl0 + cc];
                    const float hv = (1.0f - zv) * nv + zv * ho;
                    hFp[r1 * 132 + jl0 + cc] = hv;
                    hvb[cc] = hv;
                }
            }
            putA4(r0, 512 + jg0, f2tf32(hva[0]), f2tf32(hva[1]));
            putA4(r1, 512 + jg0, f2tf32(hvb[0]), f2tf32(hvb[1]));
            *(float2*)(xb + (size_t)r0 * NXX + jg0) = make_float2(hva[0], hva[1]);
            *(float2*)(xb + (size_t)r1 * NXX + jg0) = make_float2(hvb[0], hvb[1]);
        }
        cbar();   // B5: h ready everywhere
    }
}

// ---------------------------------------------------------------------------
// proj (verbatim from R14)
// ---------------------------------------------------------------------------
__global__ void __launch_bounds__(512, 1) proj_kernel(
    const float* __restrict__ bp1, const float* __restrict__ bp2,
    float* __restrict__ out)
{
    extern __shared__ unsigned XA[];
    const int tid = threadIdx.x, warp = tid >> 5, lane = tid & 31;
    const int g = lane >> 2, t = lane & 3;
    const size_t rowBase = (size_t)blockIdx.x * PROJ_ROWS;

    for (int i = tid; i < PROJ_ROWS * 512; i += 512) {
        const int r = i >> 9, cl = i & 511;
        XA[r * 516 + cl] = f2tf32(out[(rowBase + r) * NXX + cl]);
    }
    __syncthreads();

    float C[4][4][4];
#pragma unroll
    for (int m = 0; m < 4; m++)
#pragma unroll
        for (int i = 0; i < 4; i++) { C[m][i][0]=0.f; C[m][i][1]=0.f; C[m][i][2]=0.f; C[m][i][3]=0.f; }
    {
        const unsigned* bbase = g_wpack + OFF_P1 + (size_t)(4 * warp) * KT_P1 * 64 + lane * 4;
#pragma unroll 1
        for (int kp = 0; kp < KT_P1 / 2; kp++) {
            unsigned a0[4][4], a1[4][4];
#pragma unroll
            for (int m = 0; m < 4; m++) {
                ldA<516>(a0[m], XA + m * 16 * 516, 2 * kp, g, t);
                ldA<516>(a1[m], XA + m * 16 * 516, 2 * kp + 1, g, t);
            }
#pragma unroll
            for (int i = 0; i < 4; i++) {
                uint4 b = *(const uint4*)(bbase + (size_t)i * KT_P1 * 64 + (size_t)kp * 128);
#pragma unroll
                for (int m = 0; m < 4; m++) {
                    mma8(C[m][i], a0[m], b.x, b.y);
                    mma8(C[m][i], a1[m], b.z, b.w);
                }
            }
        }
    }
    __syncthreads();
#pragma unroll
    for (int m = 0; m < 4; m++)
#pragma unroll
        for (int i = 0; i < 4; i++) {
            const int j0 = 32 * warp + i * 8 + 2 * t;
            XA[(m * 16 + g) * 516 + j0]         = f2tf32(tanhf(C[m][i][0] + bp1[j0]));
            XA[(m * 16 + g) * 516 + j0 + 1]     = f2tf32(tanhf(C[m][i][1] + bp1[j0 + 1]));
            XA[(m * 16 + g + 8) * 516 + j0]     = f2tf32(tanhf(C[m][i][2] + bp1[j0]));
            XA[(m * 16 + g + 8) * 516 + j0 + 1] = f2tf32(tanhf(C[m][i][3] + bp1[j0 + 1]));
        }
    __syncthreads();

    float C2[4][2][4];
#pragma unroll
    for (int m = 0; m < 4; m++)
#pragma unroll
        for (int i = 0; i < 2; i++) { C2[m][i][0]=0.f; C2[m][i][1]=0.f; C2[m][i][2]=0.f; C2[m][i][3]=0.f; }
    {
        const unsigned* bbase = g_wpack + OFF_P2 + (size_t)(2 * warp) * KT_P2 * 64 + lane * 4;
#pragma unroll 1
        for (int kp = 0; kp < KT_P2 / 2; kp++) {
            unsigned a0[4][4], a1[4][4];
#pragma unroll
            for (int m = 0; m < 4; m++) {
                ldA<516>(a0[m], XA + m * 16 * 516, 2 * kp, g, t);
                ldA<516>(a1[m], XA + m * 16 * 516, 2 * kp + 1, g, t);
            }
#pragma unroll
            for (int i = 0; i < 2; i++) {
                uint4 b = *(const uint4*)(bbase + (size_t)i * KT_P2 * 64 + (size_t)kp * 128);
#pragma unroll
                for (int m = 0; m < 4; m++) {
                    mma8(C2[m][i], a0[m], b.x, b.y);
                    mma8(C2[m][i], a1[m], b.z, b.w);
                }
            }
        }
    }
#pragma unroll
    for (int m = 0; m < 4; m++)
#pragma unroll
        for (int i = 0; i < 2; i++) {
            const int j0 = 16 * warp + i * 8 + 2 * t;
            float* y0 = out + Y_OFF + (rowBase + m * 16 + g) * NYY;
            float* y1 = out + Y_OFF + (rowBase + m * 16 + g + 8) * NYY;
            y0[j0]     = C2[m][i][0] + bp2[j0];
            y0[j0 + 1] = C2[m][i][1] + bp2[j0 + 1];
            y1[j0]     = C2[m][i][2] + bp2[j0];
            y1[j0 + 1] = C2[m][i][3] + bp2[j0 + 1];
        }
}

extern "C" void kernel_launch(void* const* d_in, const int* in_sizes, int n_in,
                              void* d_out, int out_size) {
    int off = (n_in >= 16 && in_sizes[1] == 1) ? 2 : 1;
    const float* Y0  = (const float*)d_in[0];
    const float* Wq  = (const float*)d_in[off + 0];
    const float* bq  = (const float*)d_in[off + 1];
    const float* Wp1 = (const float*)d_in[off + 2];
    const float* bp1 = (const float*)d_in[off + 3];
    const float* Wp2 = (const float*)d_in[off + 4];
    const float* bp2 = (const float*)d_in[off + 5];
    const float* Wl1 = (const float*)d_in[off + 6];
    const float* bl1 = (const float*)d_in[off + 7];
    const float* Wl2 = (const float*)d_in[off + 8];
    const float* bl2 = (const float*)d_in[off + 9];
    const float* Wih = (const float*)d_in[off + 10];
    const float* Whh = (const float*)d_in[off + 11];
    const float* bih = (const float*)d_in[off + 12];
    const float* bhh = (const float*)d_in[off + 13];
    float* out = (float*)d_out;

    cudaFuncSetAttribute(recur_kernel, cudaFuncAttributeMaxDynamicSharedMemorySize,
                         SMEM_UNITS * 4);
    cudaFuncSetAttribute(proj_kernel, cudaFuncAttributeMaxDynamicSharedMemorySize,
                         PROJ_SMEM_UNITS * 4);

    rand_kernel<<<1024, 256>>>();
    pack_kernel<<<128, 256>>>(Wq, Wl1, Wl2, Wih, Whh, Wp1, Wp2);
    recur_kernel<<<NCTA, 512, SMEM_UNITS * 4>>>(Y0, bq, bl1, bl2, bih, bhh, out);
    proj_kernel<<<(TT * NB) / PROJ_ROWS, 512, PROJ_SMEM_UNITS * 4>>>(bp1, bp2, out);
}